// round 1
// baseline (speedup 1.0000x reference)
#include <cuda_runtime.h>
#include <cuda_bf16.h>
#include <math.h>

// Problem constants
#define NB    2
#define MSEQ  2048
#define DMODEL 1024
#define NHEAD 16
#define DPH   64
#define ROWS  (NB*MSEQ)          // 4096
#define DEXP  (2*DMODEL)         // 2048

// ---------------- scratch (static device arrays; no allocs allowed) ----------
__device__ float g_qvk[ROWS * 3 * DMODEL];   // 50 MB
__device__ float g_Q  [ROWS * DMODEL];
__device__ float g_K  [ROWS * DMODEL];
__device__ float g_V  [ROWS * DMODEL];
__device__ float g_att[ROWS * DMODEL];
__device__ float g_t1 [ROWS * DEXP];         // 32 MB (also used for 1024-wide)
__device__ float g_t2 [ROWS * DMODEL];

__device__ __forceinline__ float relu6f(float v) {
    return fminf(fmaxf(v, 0.0f), 6.0f);
}

// ---------------------------------------------------------------------------
// Generic fused GEMM: C = relu6(A @ B + bias)
// A: [rows, K] row-major with leading dim lda
// B: [K, Ncols] row-major with leading dim ldb (== Ncols)
// 128x128 tile, BK=16, 256 threads, 8x8 per thread.
// All dims are multiples of tile sizes for this problem: no bounds checks.
// ---------------------------------------------------------------------------
__global__ __launch_bounds__(256) void gemm_bias_relu6(
    const float* __restrict__ A, int lda,
    const float* __restrict__ B, int ldb,
    const float* __restrict__ bias,
    float* __restrict__ C, int ldc, int K)
{
    __shared__ float As[16][132];
    __shared__ float Bs[16][132];

    const int tid  = threadIdx.x;
    const int row0 = blockIdx.y * 128;
    const int col0 = blockIdx.x * 128;
    const int ty = tid >> 4;   // 0..15
    const int tx = tid & 15;   // 0..15

    float acc[8][8];
#pragma unroll
    for (int i = 0; i < 8; ++i)
#pragma unroll
        for (int j = 0; j < 8; ++j) acc[i][j] = 0.0f;

    for (int kc = 0; kc < K; kc += 16) {
        // load A tile (128 rows x 16 k), store transposed As[k][m]
#pragma unroll
        for (int l = 0; l < 2; ++l) {
            int i  = tid + l * 256;          // 0..511
            int r  = i >> 2;                 // 0..127
            int c4 = i & 3;                  // 0..3
            float4 v = *reinterpret_cast<const float4*>(
                &A[(size_t)(row0 + r) * lda + kc + c4 * 4]);
            As[c4 * 4 + 0][r] = v.x;
            As[c4 * 4 + 1][r] = v.y;
            As[c4 * 4 + 2][r] = v.z;
            As[c4 * 4 + 3][r] = v.w;
        }
        // load B tile (16 k x 128 n)
#pragma unroll
        for (int l = 0; l < 2; ++l) {
            int i  = tid + l * 256;
            int kk = i >> 5;                 // 0..15
            int c4 = i & 31;                 // 0..31
            float4 v = *reinterpret_cast<const float4*>(
                &B[(size_t)(kc + kk) * ldb + col0 + c4 * 4]);
            *reinterpret_cast<float4*>(&Bs[kk][c4 * 4]) = v;
        }
        __syncthreads();

#pragma unroll
        for (int kk = 0; kk < 16; ++kk) {
            float ar[8], br[8];
            *reinterpret_cast<float4*>(&ar[0]) = *reinterpret_cast<float4*>(&As[kk][ty * 8]);
            *reinterpret_cast<float4*>(&ar[4]) = *reinterpret_cast<float4*>(&As[kk][ty * 8 + 4]);
            *reinterpret_cast<float4*>(&br[0]) = *reinterpret_cast<float4*>(&Bs[kk][tx * 8]);
            *reinterpret_cast<float4*>(&br[4]) = *reinterpret_cast<float4*>(&Bs[kk][tx * 8 + 4]);
#pragma unroll
            for (int i = 0; i < 8; ++i)
#pragma unroll
                for (int j = 0; j < 8; ++j)
                    acc[i][j] = fmaf(ar[i], br[j], acc[i][j]);
        }
        __syncthreads();
    }

    // epilogue: bias + relu6, vectorized stores
#pragma unroll
    for (int i = 0; i < 8; ++i) {
        int r = row0 + ty * 8 + i;
#pragma unroll
        for (int j = 0; j < 8; j += 4) {
            int c = col0 + tx * 8 + j;
            float4 bv = *reinterpret_cast<const float4*>(&bias[c]);
            float4 o;
            o.x = relu6f(acc[i][j + 0] + bv.x);
            o.y = relu6f(acc[i][j + 1] + bv.y);
            o.z = relu6f(acc[i][j + 2] + bv.z);
            o.w = relu6f(acc[i][j + 3] + bv.w);
            *reinterpret_cast<float4*>(&C[(size_t)r * ldc + c]) = o;
        }
    }
}

// ---------------------------------------------------------------------------
// Flash-style attention, exact online softmax in fp32.
// Layout: Q/K/V buffers are [n, m, D] with channel c = d*16 + h  (head innermost)
// Output: O[n, q, h*64 + d]   (head outermost in channel)
// Grid: (NB*NHEAD, MSEQ/64), 256 threads.
// Each thread: q = tid/4 (0..63), sub = tid%4; owns k-slice [sub*16, sub*16+16)
// for scores and d-slice [sub*16, sub*16+16) for the output accumulator.
// ---------------------------------------------------------------------------
#define APAD 65
__global__ __launch_bounds__(256) void attn_kernel(
    const float* __restrict__ Qb, const float* __restrict__ Kb,
    const float* __restrict__ Vb, float* __restrict__ Ob)
{
    extern __shared__ float sm[];
    float* Qs = sm;                  // 64 x APAD
    float* Ks = Qs + 64 * APAD;
    float* Vs = Ks + 64 * APAD;
    float* Ps = Vs + 64 * APAD;

    const int nh = blockIdx.x;
    const int n  = nh >> 4;
    const int h  = nh & 15;
    const int q0 = blockIdx.y * 64;
    const int tid = threadIdx.x;
    const int q   = tid >> 2;
    const int sub = tid & 3;

    const size_t base = (size_t)n * MSEQ * DMODEL + h;
    const float* Qg = Qb + base;
    const float* Kg = Kb + base;
    const float* Vg = Vb + base;

    // load Q tile [64 q][64 d]
    for (int i = tid; i < 64 * 64; i += 256) {
        int r = i >> 6, d = i & 63;
        Qs[r * APAD + d] = Qg[(size_t)(q0 + r) * DMODEL + d * NHEAD];
    }

    float m_i = -1e30f, l_i = 0.0f;
    float acc[16];
#pragma unroll
    for (int dd = 0; dd < 16; ++dd) acc[dd] = 0.0f;

    const float rscale = 1.0f / (sqrtf(64.0f) + 1e-10f);

    for (int kt = 0; kt < MSEQ / 64; ++kt) {
        const int k0 = kt * 64;
        __syncthreads();   // protects Qs (first iter) and Ks/Vs/Ps (later iters)
        for (int i = tid; i < 64 * 64; i += 256) {
            int r = i >> 6, d = i & 63;
            Ks[r * APAD + d] = Kg[(size_t)(k0 + r) * DMODEL + d * NHEAD];
            Vs[r * APAD + d] = Vg[(size_t)(k0 + r) * DMODEL + d * NHEAD];
        }
        __syncthreads();

        // scores for this thread's 16 k values
        float s[16];
        const float* qrow = &Qs[q * APAD];
#pragma unroll
        for (int j = 0; j < 16; ++j) s[j] = 0.0f;
#pragma unroll 8
        for (int d = 0; d < 64; ++d) {
            float qv = qrow[d];
#pragma unroll
            for (int j = 0; j < 16; ++j)
                s[j] = fmaf(qv, Ks[(sub * 16 + j) * APAD + d], s[j]);
        }

        float tmax = s[0];
#pragma unroll
        for (int j = 1; j < 16; ++j) tmax = fmaxf(tmax, s[j] );
        tmax *= 1.0f;  // scores scaled below; scale is positive so max commutes
        // apply scale to max domain consistently: scale each s first
#pragma unroll
        for (int j = 0; j < 16; ++j) s[j] *= rscale;
        tmax *= rscale;
        tmax = fmaxf(tmax, __shfl_xor_sync(0xffffffffu, tmax, 1));
        tmax = fmaxf(tmax, __shfl_xor_sync(0xffffffffu, tmax, 2));

        float m_new = fmaxf(m_i, tmax);
        float corr  = __expf(m_i - m_new);
        float rs = 0.0f;
#pragma unroll
        for (int j = 0; j < 16; ++j) {
            float p = __expf(s[j] - m_new);
            Ps[q * APAD + sub * 16 + j] = p;
            rs += p;
        }
        rs += __shfl_xor_sync(0xffffffffu, rs, 1);
        rs += __shfl_xor_sync(0xffffffffu, rs, 2);
        l_i = l_i * corr + rs;
        m_i = m_new;
#pragma unroll
        for (int dd = 0; dd < 16; ++dd) acc[dd] *= corr;

        __syncthreads();  // all P written

        // acc[d-slice] += P[q, :] @ V[:, d-slice]
#pragma unroll 4
        for (int k = 0; k < 64; ++k) {
            float pv = Ps[q * APAD + k];
            const float* vrow = &Vs[k * APAD + sub * 16];
#pragma unroll
            for (int dd = 0; dd < 16; ++dd)
                acc[dd] = fmaf(pv, vrow[dd], acc[dd]);
        }
    }

    const float inv = 1.0f / l_i;
    float* Og = Ob + (size_t)n * MSEQ * DMODEL;
    const size_t obase = (size_t)(q0 + q) * DMODEL + h * DPH + sub * 16;
#pragma unroll
    for (int dd = 0; dd < 16; dd += 4) {
        float4 o;
        o.x = acc[dd + 0] * inv;
        o.y = acc[dd + 1] * inv;
        o.z = acc[dd + 2] * inv;
        o.w = acc[dd + 3] * inv;
        *reinterpret_cast<float4*>(&Og[obase + dd]) = o;
    }
}

// ---------------------------------------------------------------------------
// LayerNorm over last dim (1024). One block per row, 256 threads (4 elems/thr).
// Two-pass (mean, then variance) in registers for accuracy.
// ---------------------------------------------------------------------------
__global__ __launch_bounds__(256) void layernorm_kernel(
    const float* __restrict__ in, const float* __restrict__ w,
    const float* __restrict__ b, float* __restrict__ out)
{
    __shared__ float red[8];
    const int row = blockIdx.x;
    const int tid = threadIdx.x;
    const float* x = in + (size_t)row * DMODEL;

    float4 v = *reinterpret_cast<const float4*>(&x[tid * 4]);

    float s = v.x + v.y + v.z + v.w;
#pragma unroll
    for (int o = 16; o > 0; o >>= 1) s += __shfl_xor_sync(0xffffffffu, s, o);
    if ((tid & 31) == 0) red[tid >> 5] = s;
    __syncthreads();
    float tot = 0.0f;
#pragma unroll
    for (int i = 0; i < 8; ++i) tot += red[i];
    const float mu = tot * (1.0f / DMODEL);
    __syncthreads();

    float dx0 = v.x - mu, dx1 = v.y - mu, dx2 = v.z - mu, dx3 = v.w - mu;
    float ss = dx0 * dx0 + dx1 * dx1 + dx2 * dx2 + dx3 * dx3;
#pragma unroll
    for (int o = 16; o > 0; o >>= 1) ss += __shfl_xor_sync(0xffffffffu, ss, o);
    if ((tid & 31) == 0) red[tid >> 5] = ss;
    __syncthreads();
    float tot2 = 0.0f;
#pragma unroll
    for (int i = 0; i < 8; ++i) tot2 += red[i];
    const float var  = tot2 * (1.0f / DMODEL);
    const float rstd = rsqrtf(var + 1e-5f);

    float4 wv = *reinterpret_cast<const float4*>(&w[tid * 4]);
    float4 bv = *reinterpret_cast<const float4*>(&b[tid * 4]);
    float4 o;
    o.x = dx0 * rstd * wv.x + bv.x;
    o.y = dx1 * rstd * wv.y + bv.y;
    o.z = dx2 * rstd * wv.z + bv.z;
    o.w = dx3 * rstd * wv.w + bv.w;
    *reinterpret_cast<float4*>(&out[(size_t)row * DMODEL + tid * 4]) = o;
}

// ---------------------------------------------------------------------------
extern "C" void kernel_launch(void* const* d_in, const int* in_sizes, int n_in,
                              void* d_out, int out_size)
{
    const float* x      = (const float*)d_in[0];
    const float* qvk_w  = (const float*)d_in[1];
    const float* qvk_b  = (const float*)d_in[2];
    const float* qh_w   = (const float*)d_in[3];
    const float* qh_b   = (const float*)d_in[4];
    const float* kh_w   = (const float*)d_in[5];
    const float* kh_b   = (const float*)d_in[6];
    const float* vh_w   = (const float*)d_in[7];
    const float* vh_b   = (const float*)d_in[8];
    const float* o_w    = (const float*)d_in[9];
    const float* o_b    = (const float*)d_in[10];
    const float* ln1_w  = (const float*)d_in[11];
    const float* ln1_b  = (const float*)d_in[12];
    const float* m1_w   = (const float*)d_in[13];
    const float* m1_b   = (const float*)d_in[14];
    const float* m2_w   = (const float*)d_in[15];
    const float* m2_b   = (const float*)d_in[16];
    const float* ln2_w  = (const float*)d_in[17];
    const float* ln2_b  = (const float*)d_in[18];
    float* out = (float*)d_out;

    float *p_qvk, *p_Q, *p_K, *p_V, *p_att, *p_t1, *p_t2;
    cudaGetSymbolAddress((void**)&p_qvk, g_qvk);
    cudaGetSymbolAddress((void**)&p_Q,   g_Q);
    cudaGetSymbolAddress((void**)&p_K,   g_K);
    cudaGetSymbolAddress((void**)&p_V,   g_V);
    cudaGetSymbolAddress((void**)&p_att, g_att);
    cudaGetSymbolAddress((void**)&p_t1,  g_t1);
    cudaGetSymbolAddress((void**)&p_t2,  g_t2);

    const int attn_smem = 4 * 64 * APAD * (int)sizeof(float);  // 66560 B
    cudaFuncSetAttribute(attn_kernel,
                         cudaFuncAttributeMaxDynamicSharedMemorySize, attn_smem);

    dim3 blk(256);

    // 1) qvk = relu6(x @ qvk_w + qvk_b)           [4096 x 3072]
    gemm_bias_relu6<<<dim3(3 * DMODEL / 128, ROWS / 128), blk>>>(
        x, DMODEL, qvk_w, 3 * DMODEL, qvk_b, p_qvk, 3 * DMODEL, DMODEL);

    // 2-4) head projections                        [4096 x 1024] each
    gemm_bias_relu6<<<dim3(DMODEL / 128, ROWS / 128), blk>>>(
        p_qvk + 0 * DMODEL, 3 * DMODEL, qh_w, DMODEL, qh_b, p_Q, DMODEL, DMODEL);
    gemm_bias_relu6<<<dim3(DMODEL / 128, ROWS / 128), blk>>>(
        p_qvk + 1 * DMODEL, 3 * DMODEL, kh_w, DMODEL, kh_b, p_K, DMODEL, DMODEL);
    gemm_bias_relu6<<<dim3(DMODEL / 128, ROWS / 128), blk>>>(
        p_qvk + 2 * DMODEL, 3 * DMODEL, vh_w, DMODEL, vh_b, p_V, DMODEL, DMODEL);

    // 5) attention
    attn_kernel<<<dim3(NB * NHEAD, MSEQ / 64), blk, attn_smem>>>(p_Q, p_K, p_V, p_att);

    // 6) o-proj + relu6
    gemm_bias_relu6<<<dim3(DMODEL / 128, ROWS / 128), blk>>>(
        p_att, DMODEL, o_w, DMODEL, o_b, p_t2, DMODEL, DMODEL);

    // 7) LN1
    layernorm_kernel<<<ROWS, blk>>>(p_t2, ln1_w, ln1_b, p_att);

    // 8) m1 + relu6                               [4096 x 2048]
    gemm_bias_relu6<<<dim3(DEXP / 128, ROWS / 128), blk>>>(
        p_att, DMODEL, m1_w, DEXP, m1_b, p_t1, DEXP, DMODEL);

    // 9) m2 + relu6                               [4096 x 1024]
    gemm_bias_relu6<<<dim3(DMODEL / 128, ROWS / 128), blk>>>(
        p_t1, DEXP, m2_w, DMODEL, m2_b, p_t2, DMODEL, DEXP);

    // 10) LN2 -> out
    layernorm_kernel<<<ROWS, blk>>>(p_t2, ln2_w, ln2_b, out);
}

// round 2
// speedup vs baseline: 5.1378x; 5.1378x over previous
#include <cuda_runtime.h>
#include <cuda_bf16.h>
#include <math.h>

// Problem constants
#define NB     2
#define MSEQ   2048
#define DMODEL 1024
#define NHEAD  16
#define DPH    64
#define ROWS   (NB*MSEQ)          // 4096
#define DEXP   (2*DMODEL)         // 2048

// ---------------- scratch (static device arrays; no allocs allowed) ----------
__device__ float g_qvk[ROWS * 3 * DMODEL];
__device__ float g_Q  [ROWS * DMODEL];   // as [n,h,m,64]
__device__ float g_K  [ROWS * DMODEL];   // as [n,h,m,64]
__device__ float g_V  [ROWS * DMODEL];   // as [n,h,64,m]  (transposed)
__device__ float g_att[ROWS * DMODEL];
__device__ float g_t1 [ROWS * DEXP];
__device__ float g_t2 [ROWS * DMODEL];

__device__ __forceinline__ float relu6f(float v) {
    return fminf(fmaxf(v, 0.0f), 6.0f);
}

// round-to-nearest fp32 -> tf32 (bits in low 32, lower 13 bits zeroed by HW use)
__device__ __forceinline__ unsigned f2tf(float x) {
    unsigned u;
    asm("cvt.rna.tf32.f32 %0, %1;" : "=r"(u) : "f"(x));
    return u;
}

// D += A*B  for m16n8k8 tf32 (row.col)
__device__ __forceinline__ void mma8(float* d, const unsigned* a, const unsigned* b) {
    asm volatile(
        "mma.sync.aligned.m16n8k8.row.col.f32.tf32.tf32.f32 "
        "{%0,%1,%2,%3}, {%4,%5,%6,%7}, {%8,%9}, {%0,%1,%2,%3};\n"
        : "+f"(d[0]), "+f"(d[1]), "+f"(d[2]), "+f"(d[3])
        : "r"(a[0]), "r"(a[1]), "r"(a[2]), "r"(a[3]), "r"(b[0]), "r"(b[1]));
}

// ---------------------------------------------------------------------------
// tf32 GEMM: C = relu6(A @ B + bias)
// Block tile 128x128, BK=16, 256 threads (8 warps, 4x2 of 32x64 warp tiles).
// MODE 0: row-major C [ldc]
// MODE 1: scatter to [n,h,m,64]  (Q/K head layout; col c -> d=c>>4, h=c&15)
// MODE 2: scatter to [n,h,64,m]  (V transposed layout)
// ---------------------------------------------------------------------------
template<int MODE>
__global__ __launch_bounds__(256, 2) void gemm_tf32(
    const float* __restrict__ A, int lda,
    const float* __restrict__ B, int ldb,
    const float* __restrict__ bias,
    float* __restrict__ C, int ldc, int K)
{
    __shared__ unsigned As[16][136];   // [k][m], bank-conflict-free (136%32=8)
    __shared__ unsigned Bs[16][136];   // [k][n]

    const int tid = threadIdx.x;
    const int w    = tid >> 5;
    const int lane = tid & 31;
    const int gid  = lane >> 2;
    const int tig  = lane & 3;
    const int wm = (w & 3) * 32;
    const int wn = (w >> 2) * 64;
    const int row0 = blockIdx.y * 128;
    const int col0 = blockIdx.x * 128;

    float acc[2][8][4];
#pragma unroll
    for (int i = 0; i < 2; ++i)
#pragma unroll
        for (int j = 0; j < 8; ++j)
#pragma unroll
            for (int t = 0; t < 4; ++t) acc[i][j][t] = 0.0f;

    const int ar  = tid >> 2;          // A rows ar, ar+64
    const int ak  = (tid & 3) * 4;     // k offset
    const int bk0 = tid >> 5;          // B rows bk0, bk0+8
    const int bc  = (tid & 31) * 4;    // col offset
    const float* Ag = A + (size_t)row0 * lda;
    const float* Bg = B + col0;

    float4 pa0, pa1, pb0, pb1;
    pa0 = *(const float4*)&Ag[(size_t)ar * lda + ak];
    pa1 = *(const float4*)&Ag[(size_t)(ar + 64) * lda + ak];
    pb0 = *(const float4*)&Bg[(size_t)bk0 * ldb + bc];
    pb1 = *(const float4*)&Bg[(size_t)(bk0 + 8) * ldb + bc];

    for (int kc = 0; kc < K; kc += 16) {
        // STS (with tf32 RN conversion)
        As[ak + 0][ar] = f2tf(pa0.x);  As[ak + 1][ar] = f2tf(pa0.y);
        As[ak + 2][ar] = f2tf(pa0.z);  As[ak + 3][ar] = f2tf(pa0.w);
        As[ak + 0][ar + 64] = f2tf(pa1.x);  As[ak + 1][ar + 64] = f2tf(pa1.y);
        As[ak + 2][ar + 64] = f2tf(pa1.z);  As[ak + 3][ar + 64] = f2tf(pa1.w);
        {
            uint4 b0v = make_uint4(f2tf(pb0.x), f2tf(pb0.y), f2tf(pb0.z), f2tf(pb0.w));
            uint4 b1v = make_uint4(f2tf(pb1.x), f2tf(pb1.y), f2tf(pb1.z), f2tf(pb1.w));
            *(uint4*)&Bs[bk0][bc]     = b0v;
            *(uint4*)&Bs[bk0 + 8][bc] = b1v;
        }
        __syncthreads();

        if (kc + 16 < K) {
            pa0 = *(const float4*)&Ag[(size_t)ar * lda + kc + 16 + ak];
            pa1 = *(const float4*)&Ag[(size_t)(ar + 64) * lda + kc + 16 + ak];
            pb0 = *(const float4*)&Bg[(size_t)(kc + 16 + bk0) * ldb + bc];
            pb1 = *(const float4*)&Bg[(size_t)(kc + 16 + bk0 + 8) * ldb + bc];
        }

#pragma unroll
        for (int ks = 0; ks < 2; ++ks) {
            const int k0 = ks * 8;
            unsigned a[2][4];
#pragma unroll
            for (int i = 0; i < 2; ++i) {
                const int m = wm + i * 16 + gid;
                a[i][0] = As[k0 + tig][m];
                a[i][1] = As[k0 + tig][m + 8];
                a[i][2] = As[k0 + tig + 4][m];
                a[i][3] = As[k0 + tig + 4][m + 8];
            }
#pragma unroll
            for (int j = 0; j < 8; ++j) {
                const int nn = wn + j * 8 + gid;
                unsigned b[2];
                b[0] = Bs[k0 + tig][nn];
                b[1] = Bs[k0 + tig + 4][nn];
                mma8(acc[0][j], a[0], b);
                mma8(acc[1][j], a[1], b);
            }
        }
        __syncthreads();
    }

    // epilogue
#pragma unroll
    for (int i = 0; i < 2; ++i) {
#pragma unroll
        for (int j = 0; j < 8; ++j) {
            const int r = row0 + wm + i * 16 + gid;
            const int c = col0 + wn + j * 8 + tig * 2;
            const float b0 = bias[c], b1 = bias[c + 1];
            const float v00 = relu6f(acc[i][j][0] + b0);
            const float v01 = relu6f(acc[i][j][1] + b1);
            const float v10 = relu6f(acc[i][j][2] + b0);
            const float v11 = relu6f(acc[i][j][3] + b1);
            if (MODE == 0) {
                *(float2*)&C[(size_t)r * ldc + c]       = make_float2(v00, v01);
                *(float2*)&C[(size_t)(r + 8) * ldc + c] = make_float2(v10, v11);
            } else if (MODE == 1) {
                const int d = c >> 4, h = c & 15;   // h<15 always for even c
                const int n = r >> 11, m = r & 2047;
                const size_t b1i = ((size_t)(n * 16 + h) * 2048 + m) * 64 + d;
                C[b1i]              = v00;   // (h)
                C[b1i + 131072]     = v01;   // (h+1) plane: 2048*64
                C[b1i + 512]        = v10;   // m+8
                C[b1i + 131072+512] = v11;
            } else {
                const int d = c >> 4, h = c & 15;
                const int n = r >> 11, m = r & 2047;
                const size_t b1i = ((size_t)(n * 16 + h) * 64 + d) * 2048 + m;
                C[b1i]            = v00;
                C[b1i + 131072]   = v01;     // (h+1) plane: 64*2048
                C[b1i + 8]        = v10;     // m+8
                C[b1i + 131072+8] = v11;
            }
        }
    }
}

// ---------------------------------------------------------------------------
// Flash attention with tf32 MMA. Q tile 128, K tile 64, d=64.
// Q/K: [n,h,m,64]; V: [n,h,64,m]; out: [n,m, h*64+d]
// 8 warps: S/O warp tiles 32x32, warp grid 4(m) x 2(n).
// ---------------------------------------------------------------------------
__global__ __launch_bounds__(256, 2) void attn_tf32(
    const float* __restrict__ Qh, const float* __restrict__ Kh,
    const float* __restrict__ Vh, float* __restrict__ Ob)
{
    extern __shared__ unsigned sm_u[];
    unsigned* Qs = sm_u;                 // 128*68
    unsigned* Ks = Qs + 128 * 68;        // 64*68
    unsigned* Vt = Ks + 64 * 68;         // 64*68  ([d][kseq])
    float*    Ps = (float*)(Vt + 64 * 68); // 128*68
    float*    cr = Ps + 128 * 68;        // 128

    const int tid = threadIdx.x;
    const int w    = tid >> 5;
    const int lane = tid & 31;
    const int gid  = lane >> 2;
    const int tig  = lane & 3;
    const int wm = (w >> 1) * 32;
    const int wd = (w & 1) * 32;         // S: kseq-stripe; O: d-stripe
    const int nh = blockIdx.x, n = nh >> 4, h = nh & 15;
    const int q0 = blockIdx.y * 128;
    const float rscale = 1.0f / (8.0f + 1e-10f);

    const float* Qg = Qh + (size_t)nh * 2048 * 64;
    const float* Kg = Kh + (size_t)nh * 2048 * 64;
    const float* Vg = Vh + (size_t)nh * 64 * 2048;

    // load Q tile (coalesced) with tf32 conversion
#pragma unroll
    for (int l = 0; l < 8; ++l) {
        const int idx = tid + l * 256;
        const int r = idx >> 4, c4 = (idx & 15) * 4;
        float4 v = *(const float4*)&Qg[(size_t)(q0 + r) * 64 + c4];
        unsigned* dst = &Qs[r * 68 + c4];
        dst[0] = f2tf(v.x); dst[1] = f2tf(v.y); dst[2] = f2tf(v.z); dst[3] = f2tf(v.w);
    }

    float o[2][4][4];
#pragma unroll
    for (int i = 0; i < 2; ++i)
#pragma unroll
        for (int j = 0; j < 4; ++j)
#pragma unroll
            for (int t = 0; t < 4; ++t) o[i][j][t] = 0.0f;

    float m_i = -1e30f, l_i = 0.0f;
    const int q = tid >> 1, sub = tid & 1;

    for (int kt = 0; kt < 32; ++kt) {
        const int k0 = kt * 64;
        __syncthreads();
        // load K, V tiles (coalesced)
#pragma unroll
        for (int l = 0; l < 4; ++l) {
            const int idx = tid + l * 256;
            const int r = idx >> 4, c4 = (idx & 15) * 4;
            float4 kv = *(const float4*)&Kg[(size_t)(k0 + r) * 64 + c4];
            unsigned* dk = &Ks[r * 68 + c4];
            dk[0] = f2tf(kv.x); dk[1] = f2tf(kv.y); dk[2] = f2tf(kv.z); dk[3] = f2tf(kv.w);
            float4 vv = *(const float4*)&Vg[(size_t)r * 2048 + k0 + c4];
            unsigned* dv = &Vt[r * 68 + c4];
            dv[0] = f2tf(vv.x); dv[1] = f2tf(vv.y); dv[2] = f2tf(vv.z); dv[3] = f2tf(vv.w);
        }
        __syncthreads();

        // S = Q K^T
        float s[2][4][4];
#pragma unroll
        for (int i = 0; i < 2; ++i)
#pragma unroll
            for (int j = 0; j < 4; ++j)
#pragma unroll
                for (int t = 0; t < 4; ++t) s[i][j][t] = 0.0f;
#pragma unroll
        for (int ks = 0; ks < 8; ++ks) {
            const int kk = ks * 8;
            unsigned a[2][4];
#pragma unroll
            for (int i = 0; i < 2; ++i) {
                const int m = wm + i * 16 + gid;
                a[i][0] = Qs[m * 68 + kk + tig];
                a[i][1] = Qs[(m + 8) * 68 + kk + tig];
                a[i][2] = Qs[m * 68 + kk + tig + 4];
                a[i][3] = Qs[(m + 8) * 68 + kk + tig + 4];
            }
#pragma unroll
            for (int j = 0; j < 4; ++j) {
                const int col = wd + j * 8 + gid;
                unsigned b[2];
                b[0] = Ks[col * 68 + kk + tig];
                b[1] = Ks[col * 68 + kk + tig + 4];
                mma8(s[0][j], a[0], b);
                mma8(s[1][j], a[1], b);
            }
        }
        // store scaled S
#pragma unroll
        for (int i = 0; i < 2; ++i)
#pragma unroll
            for (int j = 0; j < 4; ++j) {
                const int r = wm + i * 16 + gid;
                const int c = wd + j * 8 + tig * 2;
                *(float2*)&Ps[r * 68 + c] =
                    make_float2(s[i][j][0] * rscale, s[i][j][1] * rscale);
                *(float2*)&Ps[(r + 8) * 68 + c] =
                    make_float2(s[i][j][2] * rscale, s[i][j][3] * rscale);
            }
        __syncthreads();

        // online softmax (each thread: row q, 32 cols)
        {
            float* pr = &Ps[q * 68 + sub * 32];
            float tmax = -1e30f;
#pragma unroll
            for (int jj = 0; jj < 8; ++jj) {
                float4 v = *(float4*)&pr[jj * 4];
                tmax = fmaxf(tmax, fmaxf(fmaxf(v.x, v.y), fmaxf(v.z, v.w)));
            }
            tmax = fmaxf(tmax, __shfl_xor_sync(0xffffffffu, tmax, 1));
            const float m_new = fmaxf(m_i, tmax);
            const float corrv = __expf(m_i - m_new);
            float rs = 0.0f;
#pragma unroll
            for (int jj = 0; jj < 8; ++jj) {
                float4 v = *(float4*)&pr[jj * 4];
                float p0 = __expf(v.x - m_new), p1 = __expf(v.y - m_new);
                float p2 = __expf(v.z - m_new), p3 = __expf(v.w - m_new);
                rs += (p0 + p1) + (p2 + p3);
                unsigned* pu = (unsigned*)&pr[jj * 4];
                pu[0] = f2tf(p0); pu[1] = f2tf(p1); pu[2] = f2tf(p2); pu[3] = f2tf(p3);
            }
            rs += __shfl_xor_sync(0xffffffffu, rs, 1);
            l_i = l_i * corrv + rs;
            m_i = m_new;
            if (sub == 0) cr[q] = corrv;
        }
        __syncthreads();

        // rescale O, then O += P @ V
        {
            const float c0 = cr[wm + gid],      c1 = cr[wm + gid + 8];
            const float c2 = cr[wm + 16 + gid], c3 = cr[wm + 16 + gid + 8];
#pragma unroll
            for (int j = 0; j < 4; ++j) {
                o[0][j][0] *= c0; o[0][j][1] *= c0; o[0][j][2] *= c1; o[0][j][3] *= c1;
                o[1][j][0] *= c2; o[1][j][1] *= c2; o[1][j][2] *= c3; o[1][j][3] *= c3;
            }
        }
        const unsigned* Pu = (const unsigned*)Ps;
#pragma unroll
        for (int ks = 0; ks < 8; ++ks) {
            const int kk = ks * 8;
            unsigned a[2][4];
#pragma unroll
            for (int i = 0; i < 2; ++i) {
                const int m = wm + i * 16 + gid;
                a[i][0] = Pu[m * 68 + kk + tig];
                a[i][1] = Pu[(m + 8) * 68 + kk + tig];
                a[i][2] = Pu[m * 68 + kk + tig + 4];
                a[i][3] = Pu[(m + 8) * 68 + kk + tig + 4];
            }
#pragma unroll
            for (int j = 0; j < 4; ++j) {
                const int dcol = wd + j * 8 + gid;
                unsigned b[2];
                b[0] = Vt[dcol * 68 + kk + tig];
                b[1] = Vt[dcol * 68 + kk + tig + 4];
                mma8(o[0][j], a[0], b);
                mma8(o[1][j], a[1], b);
            }
        }
    }

    __syncthreads();
    if (sub == 0) cr[q] = 1.0f / l_i;
    __syncthreads();

    const float i0 = cr[wm + gid],      i1 = cr[wm + gid + 8];
    const float i2 = cr[wm + 16 + gid], i3 = cr[wm + 16 + gid + 8];
    float* Og = Ob + (size_t)n * MSEQ * DMODEL;
#pragma unroll
    for (int i = 0; i < 2; ++i) {
        const float fa = (i == 0) ? i0 : i2;
        const float fb = (i == 0) ? i1 : i3;
#pragma unroll
        for (int j = 0; j < 4; ++j) {
            const int r = q0 + wm + i * 16 + gid;
            const int c = h * 64 + wd + j * 8 + tig * 2;
            *(float2*)&Og[(size_t)r * DMODEL + c] =
                make_float2(o[i][j][0] * fa, o[i][j][1] * fa);
            *(float2*)&Og[(size_t)(r + 8) * DMODEL + c] =
                make_float2(o[i][j][2] * fb, o[i][j][3] * fb);
        }
    }
}

// ---------------------------------------------------------------------------
// LayerNorm over last dim (1024). One block per row, 256 threads.
// ---------------------------------------------------------------------------
__global__ __launch_bounds__(256) void layernorm_kernel(
    const float* __restrict__ in, const float* __restrict__ w,
    const float* __restrict__ b, float* __restrict__ out)
{
    __shared__ float red[8];
    const int row = blockIdx.x;
    const int tid = threadIdx.x;
    const float* x = in + (size_t)row * DMODEL;

    float4 v = *reinterpret_cast<const float4*>(&x[tid * 4]);

    float s = v.x + v.y + v.z + v.w;
#pragma unroll
    for (int o = 16; o > 0; o >>= 1) s += __shfl_xor_sync(0xffffffffu, s, o);
    if ((tid & 31) == 0) red[tid >> 5] = s;
    __syncthreads();
    float tot = 0.0f;
#pragma unroll
    for (int i = 0; i < 8; ++i) tot += red[i];
    const float mu = tot * (1.0f / DMODEL);
    __syncthreads();

    float dx0 = v.x - mu, dx1 = v.y - mu, dx2 = v.z - mu, dx3 = v.w - mu;
    float ss = dx0 * dx0 + dx1 * dx1 + dx2 * dx2 + dx3 * dx3;
#pragma unroll
    for (int o = 16; o > 0; o >>= 1) ss += __shfl_xor_sync(0xffffffffu, ss, o);
    if ((tid & 31) == 0) red[tid >> 5] = ss;
    __syncthreads();
    float tot2 = 0.0f;
#pragma unroll
    for (int i = 0; i < 8; ++i) tot2 += red[i];
    const float rstd = rsqrtf(tot2 * (1.0f / DMODEL) + 1e-5f);

    float4 wv = *reinterpret_cast<const float4*>(&w[tid * 4]);
    float4 bv = *reinterpret_cast<const float4*>(&b[tid * 4]);
    float4 o;
    o.x = dx0 * rstd * wv.x + bv.x;
    o.y = dx1 * rstd * wv.y + bv.y;
    o.z = dx2 * rstd * wv.z + bv.z;
    o.w = dx3 * rstd * wv.w + bv.w;
    *reinterpret_cast<float4*>(&out[(size_t)row * DMODEL + tid * 4]) = o;
}

// ---------------------------------------------------------------------------
extern "C" void kernel_launch(void* const* d_in, const int* in_sizes, int n_in,
                              void* d_out, int out_size)
{
    const float* x      = (const float*)d_in[0];
    const float* qvk_w  = (const float*)d_in[1];
    const float* qvk_b  = (const float*)d_in[2];
    const float* qh_w   = (const float*)d_in[3];
    const float* qh_b   = (const float*)d_in[4];
    const float* kh_w   = (const float*)d_in[5];
    const float* kh_b   = (const float*)d_in[6];
    const float* vh_w   = (const float*)d_in[7];
    const float* vh_b   = (const float*)d_in[8];
    const float* o_w    = (const float*)d_in[9];
    const float* o_b    = (const float*)d_in[10];
    const float* ln1_w  = (const float*)d_in[11];
    const float* ln1_b  = (const float*)d_in[12];
    const float* m1_w   = (const float*)d_in[13];
    const float* m1_b   = (const float*)d_in[14];
    const float* m2_w   = (const float*)d_in[15];
    const float* m2_b   = (const float*)d_in[16];
    const float* ln2_w  = (const float*)d_in[17];
    const float* ln2_b  = (const float*)d_in[18];
    float* out = (float*)d_out;

    float *p_qvk, *p_Q, *p_K, *p_V, *p_att, *p_t1, *p_t2;
    cudaGetSymbolAddress((void**)&p_qvk, g_qvk);
    cudaGetSymbolAddress((void**)&p_Q,   g_Q);
    cudaGetSymbolAddress((void**)&p_K,   g_K);
    cudaGetSymbolAddress((void**)&p_V,   g_V);
    cudaGetSymbolAddress((void**)&p_att, g_att);
    cudaGetSymbolAddress((void**)&p_t1,  g_t1);
    cudaGetSymbolAddress((void**)&p_t2,  g_t2);

    const int attn_smem = (128*68 + 64*68 + 64*68 + 128*68 + 128) * 4;  // 104960
    cudaFuncSetAttribute(attn_tf32,
                         cudaFuncAttributeMaxDynamicSharedMemorySize, attn_smem);

    dim3 blk(256);

    // 1) qvk = relu6(x @ qvk_w + qvk_b)       [4096 x 3072]
    gemm_tf32<0><<<dim3(3 * DMODEL / 128, ROWS / 128), blk>>>(
        x, DMODEL, qvk_w, 3 * DMODEL, qvk_b, p_qvk, 3 * DMODEL, DMODEL);

    // 2-4) head projections with layout scatter
    gemm_tf32<1><<<dim3(DMODEL / 128, ROWS / 128), blk>>>(
        p_qvk + 0 * DMODEL, 3 * DMODEL, qh_w, DMODEL, qh_b, p_Q, 0, DMODEL);
    gemm_tf32<1><<<dim3(DMODEL / 128, ROWS / 128), blk>>>(
        p_qvk + 1 * DMODEL, 3 * DMODEL, kh_w, DMODEL, kh_b, p_K, 0, DMODEL);
    gemm_tf32<2><<<dim3(DMODEL / 128, ROWS / 128), blk>>>(
        p_qvk + 2 * DMODEL, 3 * DMODEL, vh_w, DMODEL, vh_b, p_V, 0, DMODEL);

    // 5) attention
    attn_tf32<<<dim3(NB * NHEAD, MSEQ / 128), blk, attn_smem>>>(p_Q, p_K, p_V, p_att);

    // 6) o-proj + relu6
    gemm_tf32<0><<<dim3(DMODEL / 128, ROWS / 128), blk>>>(
        p_att, DMODEL, o_w, DMODEL, o_b, p_t2, DMODEL, DMODEL);

    // 7) LN1
    layernorm_kernel<<<ROWS, blk>>>(p_t2, ln1_w, ln1_b, p_att);

    // 8) m1 + relu6                           [4096 x 2048]
    gemm_tf32<0><<<dim3(DEXP / 128, ROWS / 128), blk>>>(
        p_att, DMODEL, m1_w, DEXP, m1_b, p_t1, DEXP, DMODEL);

    // 9) m2 + relu6                           [4096 x 1024], K=2048
    gemm_tf32<0><<<dim3(DMODEL / 128, ROWS / 128), blk>>>(
        p_t1, DEXP, m2_w, DMODEL, m2_b, p_t2, DMODEL, DEXP);

    // 10) LN2 -> out
    layernorm_kernel<<<ROWS, blk>>>(p_t2, ln2_w, ln2_b, out);
}